// round 5
// baseline (speedup 1.0000x reference)
#include <cuda_runtime.h>
#include <cuda_bf16.h>

// CL4CTR loss on GB300 — single fused kernel, warp-PAIR per sample.
//   x:   [4096, 39] int32 field indices      (d_in[0])
//   emb: [3900000, 16] float32               (d_in[1])
//   out: scalar float32
//
// 512 blocks x 512 threads = 16 warps = 8 samples per block (2 warps/sample).
// Each warp of a pair gathers half the k-chunks, computes half the norms, and
// runs half of the 55+9pad Gram tiles. 8192 total warps (~75% occ) hide the
// random-gather DRAM latency that capped the 1-warp-per-sample version at
// issue=29%. Last block (atomic counter) reduces s^2, combines, writes the
// scalar, and re-zeroes all accumulators (zero-invariant across graph replays).

#define F_FIELDS 39
#define FP 40            // padded rows
#define NGRP 10          // 4-row groups
#define SAMPLES 8        // samples per block
#define NTHREADS 512
#define NBLOCKS 512
#define EPSV 1e-4f

__device__ float g_s[624];       // s[f][d]
__device__ float g_acc[2];       // [0]=sum(sq), [1]=uniform sum
__device__ unsigned g_count;     // arrival counter (returns to 0 each run)

#define TT(i,j,w) ((unsigned)((i) | ((j)<<8) | ((w)<<16)))
__constant__ unsigned c_tiles[64] = {
  TT(0,0,1),TT(0,1,2),TT(0,2,2),TT(0,3,2),TT(0,4,2),TT(0,5,2),TT(0,6,2),TT(0,7,2),TT(0,8,2),TT(0,9,2),
  TT(1,1,1),TT(1,2,2),TT(1,3,2),TT(1,4,2),TT(1,5,2),TT(1,6,2),TT(1,7,2),TT(1,8,2),TT(1,9,2),
  TT(2,2,1),TT(2,3,2),TT(2,4,2),TT(2,5,2),TT(2,6,2),TT(2,7,2),TT(2,8,2),TT(2,9,2),
  TT(3,3,1),TT(3,4,2),TT(3,5,2),TT(3,6,2),TT(3,7,2),TT(3,8,2),TT(3,9,2),
  TT(4,4,1),TT(4,5,2),TT(4,6,2),TT(4,7,2),TT(4,8,2),TT(4,9,2),
  TT(5,5,1),TT(5,6,2),TT(5,7,2),TT(5,8,2),TT(5,9,2),
  TT(6,6,1),TT(6,7,2),TT(6,8,2),TT(6,9,2),
  TT(7,7,1),TT(7,8,2),TT(7,9,2),
  TT(8,8,1),TT(8,9,2),
  TT(9,9,1),
  TT(0,0,0),TT(0,0,0),TT(0,0,0),TT(0,0,0),TT(0,0,0),TT(0,0,0),TT(0,0,0),TT(0,0,0),TT(0,0,0)
};

// Reciprocal without MUFU: magic seed + 2 Newton steps (max rel err ~6e-6).
__device__ __forceinline__ float frcp_nt(float d) {
    float r = __int_as_float(0x7EF311C3 - __float_as_int(d));
    r = r * fmaf(-d, r, 2.0f);
    r = r * fmaf(-d, r, 2.0f);
    return r;
}

__global__ void __launch_bounds__(NTHREADS) cl4_fused(const int* __restrict__ x,
                                                      const float* __restrict__ emb,
                                                      float* __restrict__ out) {
    __shared__ __align__(16) float s_xt[SAMPLES][16 * FP]; // transposed tile [k][r]
    __shared__ float s_n[SAMPLES][FP];
    __shared__ float s_red[16][2];
    __shared__ int   s_idx[SAMPLES][40];
    __shared__ unsigned s_last;
    __shared__ float s_fin[16];

    const int wid  = threadIdx.x >> 5;       // 0..15
    const int lane = threadIdx.x & 31;
    const int s    = wid >> 1;               // sample slot 0..7
    const int h    = wid & 1;                // half of the warp pair
    const int b    = blockIdx.x * SAMPLES + s;   // 512*8 = 4096 samples
    const int* xr  = x + b * F_FIELDS;

    // ---- phase 1: indices (warp pair splits the 39 loads), add field offsets
    {
        int f = lane + 32 * h;
        if (f < F_FIELDS) s_idx[s][f] = __ldg(&xr[f]) + f * 100000;
    }
    __syncthreads();

    // ---- phase 2: gather. Pair splits k-chunks: warp h loads c in {2h, 2h+1}
    // (k rows 8h..8h+7). 78 float4 LDGs per warp; lanes (2r,2r+1) hit one row.
    #pragma unroll
    for (int it = 0; it < 3; it++) {
        int i = it * 32 + lane;
        if (i < 78) {
            int r = i >> 1, c = (i & 1) + 2 * h;
            int row = s_idx[s][r];
            float4 v = *reinterpret_cast<const float4*>(emb + (size_t)row * 16 + c * 4);
            float* dst = &s_xt[s][c * 4 * FP + r];
            dst[0]      = v.x;
            dst[FP]     = v.y;
            dst[2 * FP] = v.z;
            dst[3 * FP] = v.w;
        }
    }
    if (lane < 8) s_xt[s][(8 * h + lane) * FP + 39] = 0.0f;   // zero pad row
    __syncthreads();

    // ---- phase 3: norms (pair splits rows: h=0 -> 0..31, h=1 -> 32..39)
    float sumsq = 0.0f;
    {
        int rr = lane + 32 * h;
        if (rr < FP) {
            float sq = 0.0f;
            #pragma unroll
            for (int k = 0; k < 16; k++) {
                float v = s_xt[s][k * FP + rr];
                sq = fmaf(v, v, sq);
            }
            s_n[s][rr] = sqrtf(sq);
            sumsq = sq;                              // pad row contributes 0
        }
    }
    __syncthreads();

    // ---- phase 4: Gram, warp h handles tile entries c_tiles[32h + lane]
    const float4* xt4 = reinterpret_cast<const float4*>(s_xt[s]);  // [16][10]
    float usum = 0.0f;
    {
        unsigned e = c_tiles[(h << 5) + lane];
        int I = e & 255, J = (e >> 8) & 255;
        float wgt = (float)(e >> 16);

        float acc[4][4];
        #pragma unroll
        for (int i = 0; i < 4; i++)
            #pragma unroll
            for (int j = 0; j < 4; j++) acc[i][j] = 0.0f;

        #pragma unroll
        for (int k = 0; k < 16; k++) {
            float4 a  = xt4[k * NGRP + I];
            float4 bb = xt4[k * NGRP + J];
            float af[4] = {a.x, a.y, a.z, a.w};
            float bf[4] = {bb.x, bb.y, bb.z, bb.w};
            #pragma unroll
            for (int i = 0; i < 4; i++)
                #pragma unroll
                for (int j = 0; j < 4; j++)
                    acc[i][j] = fmaf(af[i], bf[j], acc[i][j]);
        }

        float nf[4], ng[4];
        #pragma unroll
        for (int i = 0; i < 4; i++) {
            nf[i] = s_n[s][4 * I + i];
            ng[i] = s_n[s][4 * J + i];
        }

        float ts = 0.0f;
        #pragma unroll
        for (int i = 0; i < 4; i++)
            #pragma unroll
            for (int j = 0; j < 4; j++) {
                float den = fmaf(nf[i], ng[j], EPSV);
                ts = fmaf(acc[i][j], frcp_nt(den), ts);
            }
        usum = wgt * ts;
    }

    // ---- warp reductions
    #pragma unroll
    for (int o = 16; o; o >>= 1) {
        usum  += __shfl_xor_sync(0xffffffffu, usum, o);
        sumsq += __shfl_xor_sync(0xffffffffu, sumsq, o);
    }
    if (lane == 0) { s_red[wid][0] = sumsq; s_red[wid][1] = usum; }
    __syncthreads();

    // ---- block-level s[39][16] partial + scalar partials -> global atomics
    for (int e = threadIdx.x; e < 624; e += NTHREADS) {
        int f = e >> 4, k = e & 15;
        float v = 0.0f;
        #pragma unroll
        for (int ss = 0; ss < SAMPLES; ss++) v += s_xt[ss][k * FP + f];
        atomicAdd(&g_s[e], v);
    }
    if (threadIdx.x == 0) {
        float a = 0.0f, u = 0.0f;
        #pragma unroll
        for (int ww = 0; ww < 16; ww++) { a += s_red[ww][0]; u += s_red[ww][1]; }
        atomicAdd(&g_acc[0], a);
        atomicAdd(&g_acc[1], u);
    }

    // ---- last-block election
    __threadfence();
    __syncthreads();
    if (threadIdx.x == 0) s_last = atomicAdd(&g_count, 1u);
    __syncthreads();
    if (s_last != NBLOCKS - 1) return;

    // ---- final: sum(s^2), combine, write scalar, RE-ZERO accumulators
    float ssq = 0.0f;
    for (int e = threadIdx.x; e < 624; e += NTHREADS) {
        float v = g_s[e];
        ssq = fmaf(v, v, ssq);
        g_s[e] = 0.0f;                                // restore zero-invariant
    }
    #pragma unroll
    for (int o = 16; o; o >>= 1) ssq += __shfl_xor_sync(0xffffffffu, ssq, o);
    if (lane == 0) s_fin[wid] = ssq;
    __syncthreads();

    if (threadIdx.x == 0) {
        float st = 0.0f;
        #pragma unroll
        for (int ww = 0; ww < 16; ww++) st += s_fin[ww];
        double sumsq_t = (double)g_acc[0];
        double usum_t  = (double)g_acc[1];
        double pair    = 4096.0 * sumsq_t - (double)st;
        double align   = pair / (8386560.0 * 39.0);        // n_pairs * F
        double uni     = usum_t / (4096.0 * 39.0 * 39.0);  // B * F * F
        out[0] = (float)((align + uni) * 0.01);            // * BETA
        g_acc[0] = 0.0f;
        g_acc[1] = 0.0f;
        g_count  = 0u;                                     // reset for next replay
    }
}

extern "C" void kernel_launch(void* const* d_in, const int* in_sizes, int n_in,
                              void* d_out, int out_size) {
    const int*   x   = (const int*)d_in[0];
    const float* emb = (const float*)d_in[1];
    cl4_fused<<<NBLOCKS, NTHREADS>>>(x, emb, (float*)d_out);
}